// round 16
// baseline (speedup 1.0000x reference)
#include <cuda_runtime.h>
#include <cuda_fp16.h>
#include <cstdint>

// ---------------- problem constants ----------------
#define BB 4
#define TT 1024
#define DD 1024
#define HH 16
#define DK 64
#define DV 64
#define II 2816
#define ROWS (BB*TT)          // 4096

// B2 region offsets (halfs)
#define OFF_QKV 0
#define OFF_O   (3072*1024)
#define OFF_G   (OFF_O + 1024*1024)
#define OFF_D   (OFF_G + 5632*1024)
#define B2_TOTAL (OFF_D + 1024*2816)

// ---------------- scratch (device globals; no runtime alloc) ----------------
__device__ float  g_h1[ROWS*DD];
__device__ __half g_qkvh[(size_t)ROWS*3*DD];     // fp16 QKV GEMM output
__device__ __half g_qch[ROWS*DD];
__device__ __half g_kch[ROWS*DD];
__device__ __half g_vch[ROWS*DD];
__device__ float  g_beta[ROWS*HH];
__device__ float  g_gex[ROWS*HH];
__device__ float  g_o [ROWS*DD];
__device__ float  g_h2[ROWS*DD];
__device__ __half g_gmlh[(size_t)ROWS*2*II];     // fp16 Wg GEMM output
__device__ float  g_sdump[BB*HH*DK*DV];
__device__ __half g_A2[(size_t)ROWS*1024];       // hi-only activations, stride 1024
__device__ __half g_A3[(size_t)ROWS*II];         // mact, stride 2816
__device__ __half g_B2[(size_t)B2_TOTAL];        // all weights fp16, [N,K] each

// ================= helpers =================
__device__ __forceinline__ uint32_t smem_u32(const void* p) {
    uint32_t a;
    asm("{ .reg .u64 t; cvta.to.shared.u64 t, %1; cvt.u32.u64 %0, t; }" : "=r"(a) : "l"(p));
    return a;
}
__device__ __forceinline__ void cp16(uint32_t dst, const void* src) {
    asm volatile("cp.async.cg.shared.global [%0], [%1], 16;" :: "r"(dst), "l"(src) : "memory");
}
__device__ __forceinline__ void ldm_x4(uint32_t* r, uint32_t a) {
    asm volatile("ldmatrix.sync.aligned.m8n8.x4.shared.b16 {%0,%1,%2,%3}, [%4];"
                 : "=r"(r[0]), "=r"(r[1]), "=r"(r[2]), "=r"(r[3]) : "r"(a));
}
__device__ __forceinline__ void mma_f16(float* c, const uint32_t* a, const uint32_t* b) {
    asm volatile(
        "mma.sync.aligned.m16n8k16.row.col.f32.f16.f16.f32 "
        "{%0,%1,%2,%3}, {%4,%5,%6,%7}, {%8,%9}, {%0,%1,%2,%3};"
        : "+f"(c[0]), "+f"(c[1]), "+f"(c[2]), "+f"(c[3])
        : "r"(a[0]), "r"(a[1]), "r"(a[2]), "r"(a[3]), "r"(b[0]), "r"(b[1]));
}

// ================= fp16 HMMA GEMM =================
// C[4096,Nfull] = A[M,K] * B[N,K]^T.  Chalf != 0: fp16 output (no Add).
// Else fp32 output (+Add).  CTA 128x128, 4 warps (2x2 of 64x64), BK=64,
// 3-stage cp.async, 2 CTAs/SM.
#define STG_BYTES 32768
#define GSMEM (3*STG_BYTES)    // 96 KB

__global__ void __launch_bounds__(128, 2)
tc_gemm(const __half* __restrict__ A, const __half* __restrict__ B,
        const float* __restrict__ Add, float* __restrict__ C,
        __half* __restrict__ Chalf, int Nfull, int K)
{
    extern __shared__ __align__(1024) char smem[];
    uint32_t sb = smem_u32(smem);
    const int tid = threadIdx.x;
    const int lane = tid & 31, w = tid >> 5;
    const int wm = w & 1, wn = w >> 1;
    const int m0 = blockIdx.y * 128, n0 = blockIdx.x * 128;
    const int NK = K >> 6;

    const __half* Ab = A + (size_t)m0 * K;
    const __half* Bb = B + (size_t)n0 * K;

    const int cr = tid >> 3, cc = tid & 7;
    const uint32_t cdst = (uint32_t)(cr * 128 + ((cc ^ (cr & 7)) << 4));

    float acc[4][8][4];
    #pragma unroll
    for (int i = 0; i < 4; i++)
        #pragma unroll
        for (int j = 0; j < 8; j++)
            #pragma unroll
            for (int l = 0; l < 4; l++) acc[i][j][l] = 0.f;

    const int rowA = wm * 64 + (lane & 15);
    const int rowB = wn * 64 + (lane & 7) + ((lane >> 4) << 3);
    uint32_t aChunk[4], bChunk[4];
    #pragma unroll
    for (int ks = 0; ks < 4; ks++) {
        aChunk[ks] = (uint32_t)(((ks * 2 + (lane >> 4)) ^ (rowA & 7)) << 4);
        bChunk[ks] = (uint32_t)(((ks * 2 + ((lane >> 3) & 1)) ^ (rowB & 7)) << 4);
    }

    #define LOAD_STAGE(kt, s) {                                                   \
        uint32_t sa = sb + (s) * STG_BYTES, sbB = sa + 16384;                      \
        const __half* Asrc = Ab + (size_t)cr * K + (kt) * 64 + cc * 8;             \
        const __half* Bsrc = Bb + (size_t)cr * K + (kt) * 64 + cc * 8;             \
        _Pragma("unroll")                                                          \
        for (int t = 0; t < 8; t++) {                                              \
            cp16(sa  + cdst + t * 2048, Asrc + (size_t)(t * 16) * K);              \
            cp16(sbB + cdst + t * 2048, Bsrc + (size_t)(t * 16) * K);              \
        }                                                                          \
        asm volatile("cp.async.commit_group;" ::: "memory");                       \
    }

    LOAD_STAGE(0, 0);
    LOAD_STAGE(1, 1);

    for (int kt = 0; kt < NK; kt++) {
        int s = kt - (kt / 3) * 3;
        asm volatile("cp.async.wait_group 1;" ::: "memory");
        __syncthreads();
        if (kt + 2 < NK) {
            int s2 = (kt + 2) - ((kt + 2) / 3) * 3;
            LOAD_STAGE(kt + 2, s2);
        } else {
            asm volatile("cp.async.commit_group;" ::: "memory");
        }
        uint32_t sa = sb + s * STG_BYTES, sbB = sa + 16384;
        uint32_t baseA = sa + (uint32_t)rowA * 128;
        uint32_t baseB = sbB + (uint32_t)rowB * 128;
        #pragma unroll
        for (int ks = 0; ks < 4; ks++) {
            uint32_t a[4][4], b[8][2];
            #pragma unroll
            for (int mt = 0; mt < 4; mt++)
                ldm_x4(a[mt], baseA + mt * 2048 + aChunk[ks]);
            #pragma unroll
            for (int np = 0; np < 4; np++) {
                uint32_t r[4];
                ldm_x4(r, baseB + np * 2048 + bChunk[ks]);
                b[2*np][0] = r[0]; b[2*np][1] = r[1];
                b[2*np+1][0] = r[2]; b[2*np+1][1] = r[3];
            }
            #pragma unroll
            for (int mt = 0; mt < 4; mt++)
                #pragma unroll
                for (int nt = 0; nt < 8; nt++)
                    mma_f16(acc[mt][nt], a[mt], b[nt]);
        }
        __syncthreads();
    }

    // ---- epilogue ----
    const int l4 = lane >> 2, l2 = (lane & 3) * 2;
    if (Chalf) {
        #pragma unroll
        for (int mt = 0; mt < 4; mt++) {
            size_t r0 = (size_t)(m0 + wm * 64 + mt * 16 + l4);
            #pragma unroll
            for (int nt = 0; nt < 8; nt++) {
                size_t cidx = r0 * Nfull + (n0 + wn * 64 + nt * 8 + l2);
                *(__half2*)(Chalf + cidx) = __floats2half2_rn(acc[mt][nt][0], acc[mt][nt][1]);
                *(__half2*)(Chalf + cidx + 8 * Nfull) = __floats2half2_rn(acc[mt][nt][2], acc[mt][nt][3]);
            }
        }
    } else {
        #pragma unroll
        for (int mt = 0; mt < 4; mt++) {
            size_t r0 = (size_t)(m0 + wm * 64 + mt * 16 + l4);
            #pragma unroll
            for (int nt = 0; nt < 8; nt++) {
                size_t cidx = r0 * Nfull + (n0 + wn * 64 + nt * 8 + l2);
                float2 v0 = make_float2(acc[mt][nt][0], acc[mt][nt][1]);
                float2 v1 = make_float2(acc[mt][nt][2], acc[mt][nt][3]);
                if (Add) {
                    float2 a0 = *(const float2*)(Add + cidx);
                    float2 a1 = *(const float2*)(Add + cidx + 8 * Nfull);
                    v0.x += a0.x; v0.y += a0.y; v1.x += a1.x; v1.y += a1.y;
                }
                *(float2*)(C + cidx) = v0;
                *(float2*)(C + cidx + 8 * Nfull) = v1;
            }
        }
    }
}

// ================= fused norm + fp16 conversion =================
__global__ __launch_bounds__(256) void rmsnorm_halfA(
    const float* __restrict__ in, const float* __restrict__ w,
    float* __restrict__ hout, __half* __restrict__ A2)
{
    int row = blockIdx.x;
    __shared__ float red[8];
    const float* p = in + (size_t)row * DD;
    float v0 = p[threadIdx.x];
    float v1 = p[threadIdx.x + 256];
    float v2 = p[threadIdx.x + 512];
    float v3 = p[threadIdx.x + 768];
    float ss = v0*v0 + v1*v1 + v2*v2 + v3*v3;
    #pragma unroll
    for (int off = 16; off; off >>= 1) ss += __shfl_xor_sync(0xffffffffu, ss, off);
    if ((threadIdx.x & 31) == 0) red[threadIdx.x >> 5] = ss;
    __syncthreads();
    float tot = 0.f;
    #pragma unroll
    for (int i = 0; i < 8; i++) tot += red[i];
    float r = rsqrtf(tot * (1.0f/1024.0f) + 1e-6f);
    __half* a = A2 + (size_t)row * 1024;
    float* q = hout ? hout + (size_t)row * DD : nullptr;
    float vals[4] = {v0, v1, v2, v3};
    #pragma unroll
    for (int i = 0; i < 4; i++) {
        int c = threadIdx.x + i * 256;
        float val = vals[i] * r * w[c];
        if (q) q[c] = val;
        a[c] = __float2half_rn(val);
    }
}

__global__ __launch_bounds__(256) void ornorm_halfA(
    const float* __restrict__ o, const float* __restrict__ w, __half* __restrict__ A2)
{
    int row = blockIdx.x, t = threadIdx.x;
    float4 vv = *(const float4*)(o + (size_t)row * 1024 + t * 4);
    float ss = vv.x*vv.x + vv.y*vv.y + vv.z*vv.z + vv.w*vv.w;
    ss += __shfl_xor_sync(0xffffffffu, ss, 1);
    ss += __shfl_xor_sync(0xffffffffu, ss, 2);
    ss += __shfl_xor_sync(0xffffffffu, ss, 4);
    ss += __shfl_xor_sync(0xffffffffu, ss, 8);
    float r = rsqrtf(ss * (1.0f/64.0f) + 1e-6f);
    __half2 h0 = __floats2half2_rn(vv.x * r * w[(t*4) & 63],   vv.y * r * w[(t*4+1) & 63]);
    __half2 h1 = __floats2half2_rn(vv.z * r * w[(t*4+2) & 63], vv.w * r * w[(t*4+3) & 63]);
    __half2* a = (__half2*)(A2 + (size_t)row * 1024 + t * 4);
    a[0] = h0; a[1] = h1;
}

// SwiGLU: fp16 gml in -> fp16 A3, stride 2816
__global__ __launch_bounds__(256) void swiglu_halfA(
    const __half* __restrict__ gml, __half* __restrict__ A3)
{
    int col2 = blockIdx.x * 256 + threadIdx.x;
    int row = blockIdx.y;
    if (col2 >= 1408) return;
    const __half2* gp = (const __half2*)(gml + (size_t)row * 5632 + col2 * 2);
    float2 g = __half22float2(gp[0]);
    float2 y = __half22float2(*(const __half2*)(gml + (size_t)row * 5632 + 2816 + col2 * 2));
    float m0 = g.x / (1.f + expf(-g.x)) * y.x;
    float m1 = g.y / (1.f + expf(-g.y)) * y.y;
    *(__half2*)(A3 + (size_t)row * 2816 + col2 * 2) = __floats2half2_rn(m0, m1);
}

// W[K,N] -> B2[n][k] fp16 (transposed, single copy)
__global__ __launch_bounds__(256) void convB_kernel(
    const float* __restrict__ W, __half* __restrict__ B2, int K, int N)
{
    __shared__ float tile[32][33];
    int k0 = blockIdx.y * 32, n0 = blockIdx.x * 32;
    int tx = threadIdx.x & 31, ty = threadIdx.x >> 5;
    for (int i = ty; i < 32; i += 8)
        tile[i][tx] = W[(size_t)(k0 + i) * N + n0 + tx];
    __syncthreads();
    for (int i = ty; i < 32; i += 8) {
        size_t rb = (size_t)(n0 + i) * K;
        B2[rb + k0 + tx] = __float2half_rn(tile[tx][i]);
    }
}

__global__ __launch_bounds__(256) void convB_qkv_kernel(
    const float* __restrict__ Wq, const float* __restrict__ Wk, const float* __restrict__ Wv,
    __half* __restrict__ B2)
{
    const float* W = (blockIdx.z == 0) ? Wq : (blockIdx.z == 1) ? Wk : Wv;
    __shared__ float tile[32][33];
    int k0 = blockIdx.y * 32, n0 = blockIdx.x * 32;
    int tx = threadIdx.x & 31, ty = threadIdx.x >> 5;
    for (int i = ty; i < 32; i += 8)
        tile[i][tx] = W[(size_t)(k0 + i) * 1024 + n0 + tx];
    __syncthreads();
    for (int i = ty; i < 32; i += 8) {
        size_t rb = (size_t)(blockIdx.z * 1024 + n0 + i) * 1024;
        B2[rb + k0 + tx] = __float2half_rn(tile[tx][i]);
    }
}

// ---------------- fused b/a projections + gate math ----------------
__global__ __launch_bounds__(256) void proj_beta_kernel(
    const float* __restrict__ h, const float* __restrict__ Wb, const float* __restrict__ Wa,
    const float* __restrict__ dtb, const float* __restrict__ Alog,
    float* __restrict__ beta, float* __restrict__ gex)
{
    int row = blockIdx.x;
    __shared__ float sh[1024];
    for (int i = threadIdx.x; i < 1024; i += 256) sh[i] = h[(size_t)row * DD + i];
    __syncthreads();
    int grp = threadIdx.x >> 3, l = threadIdx.x & 7;
    const float* W = (grp < 16) ? Wb : Wa;
    int col = grp & 15;
    float s = 0.f;
    for (int k = l; k < 1024; k += 8) s += sh[k] * W[k * HH + col];
    s += __shfl_xor_sync(0xffffffffu, s, 1);
    s += __shfl_xor_sync(0xffffffffu, s, 2);
    s += __shfl_xor_sync(0xffffffffu, s, 4);
    if (l == 0) {
        if (grp < 16) {
            beta[(size_t)row * HH + col] = 2.f / (1.f + expf(-s));
        } else {
            float xv = s + dtb[col];
            float sp = (xv > 20.f) ? xv : log1pf(expf(xv));
            gex[(size_t)row * HH + col] = expf(-expf(Alog[col]) * sp);
        }
    }
}

// ---------------- causal depthwise conv (K=4) + SiLU, fp16 in/out ----------------
__global__ __launch_bounds__(256) void conv_silu3_kernel(
    const __half* __restrict__ qkv,
    __half* __restrict__ qc, __half* __restrict__ kc, __half* __restrict__ vc,
    const float* __restrict__ cq, const float* __restrict__ ck, const float* __restrict__ cv)
{
    int which = blockIdx.y;
    const float* w = (which == 0) ? cq : (which == 1) ? ck : cv;
    __half* out = (which == 0) ? qc : (which == 1) ? kc : vc;
    int inOff = which * 1024;

    int idx = blockIdx.x * 256 + threadIdx.x;
    int c   = idx & 1023;
    int tch = (idx >> 10) & 15;
    int b   = idx >> 14;
    int t0  = tch * 64;
    float w0 = w[c*4+0], w1 = w[c*4+1], w2 = w[c*4+2], w3 = w[c*4+3];
    size_t ibase = ((size_t)b * TT) * 3072 + inOff + c;
    size_t obase = ((size_t)b * TT) * DD + c;
    float xm3 = (t0 >= 3) ? __half2float(qkv[ibase + (size_t)(t0-3)*3072]) : 0.f;
    float xm2 = (t0 >= 2) ? __half2float(qkv[ibase + (size_t)(t0-2)*3072]) : 0.f;
    float xm1 = (t0 >= 1) ? __half2float(qkv[ibase + (size_t)(t0-1)*3072]) : 0.f;
    #pragma unroll 8
    for (int j = 0; j < 64; j++) {
        float xt = __half2float(qkv[ibase + (size_t)(t0+j)*3072]);
        float s  = xm3*w0 + xm2*w1 + xm1*w2 + xt*w3;
        out[obase + (size_t)(t0+j)*DD] = __float2half_rn(s / (1.f + expf(-s)));
        xm3 = xm2; xm2 = xm1; xm1 = xt;
    }
}

// ---------------- L2 norm of q (with scale) and k, fp16 in/out ----------------
__global__ __launch_bounds__(256) void l2norm_qk_kernel(
    __half* __restrict__ qc, __half* __restrict__ kc)
{
    int gw = blockIdx.x * 8 + (threadIdx.x >> 5);
    int lane = threadIdx.x & 31;
    __half* arr = (gw < 65536) ? qc : kc;
    size_t base = (size_t)(gw & 65535) * 64;
    float a = __half2float(arr[base + lane]), b = __half2float(arr[base + 32 + lane]);
    float ss = a*a + b*b;
    #pragma unroll
    for (int off = 16; off; off >>= 1) ss += __shfl_xor_sync(0xffffffffu, ss, off);
    float r = rsqrtf(ss + 1e-6f);
    if (gw < 65536) r *= 0.125f;
    arr[base + lane]      = __float2half_rn(a * r);
    arr[base + 32 + lane] = __float2half_rn(b * r);
}

// ---------------- gated delta-rule scan ----------------
// 64 blocks = (b,h); 256 thr: dv = (w<<3)|(lane&7) in 0..63, seg = lane>>3 (k-chunk of 16).
__global__ __launch_bounds__(256) void scan_kernel(
    const __half* __restrict__ q, const __half* __restrict__ k, const __half* __restrict__ v,
    const float* __restrict__ beta, const float* __restrict__ gex,
    float* __restrict__ o, float* __restrict__ state)
{
    int h    = blockIdx.x & 15;
    int b    = blockIdx.x >> 4;
    int tid  = threadIdx.x, lane = tid & 31, w = tid >> 5;
    int dv   = (w << 3) | (lane & 7);
    int kbase = (lane >> 3) << 4;          // seg*16

    __shared__ float sQ[2][8][64], sK[2][8][64], sV[2][8][64], sBe[2][8], sG[2][8];

    float S[16];
    #pragma unroll
    for (int j = 0; j < 16; j++) S[j] = 0.f;

    size_t chan = (size_t)h * 64;

    #define SCAN_LOAD(st, bf) {                                                          \
        size_t tb = (size_t)b * TT + (st) * 8;                                           \
        for (int i = tid; i < 1552; i += 256) {                                          \
            if (i < 512)                                                                 \
                sQ[bf][i>>6][i&63] = __half2float(q[(tb + (i>>6))*DD + chan + (i&63)]);  \
            else if (i < 1024) { int j2 = i-512;                                         \
                sK[bf][j2>>6][j2&63] = __half2float(k[(tb + (j2>>6))*DD + chan + (j2&63)]); } \
            else if (i < 1536) { int j2 = i-1024;                                        \
                sV[bf][j2>>6][j2&63] = __half2float(v[(tb + (j2>>6))*DD + chan + (j2&63)]); } \
            else { int j2 = i-1536;                                                      \
                if (j2 < 8) sBe[bf][j2] = beta[(tb + j2)*HH + h];                        \
                else        sG[bf][j2-8] = gex[(tb + j2-8)*HH + h]; }                    \
        }                                                                                \
    }

    SCAN_LOAD(0, 0);

    for (int st = 0; st < 128; st++) {
        int buf = st & 1;
        __syncthreads();
        if (st + 1 < 128) SCAN_LOAD(st + 1, buf ^ 1);
        #pragma unroll 2
        for (int tt = 0; tt < 8; tt++) {
            float ge = sG[buf][tt], bt = sBe[buf][tt];
            float kv0 = 0.f, kv1 = 0.f;
            #pragma unroll
            for (int j = 0; j < 8; j++)  { S[j]   *= ge; kv0 = fmaf(sK[buf][tt][kbase+j],   S[j],   kv0); }
            #pragma unroll
            for (int j = 8; j < 16; j++) { S[j]   *= ge; kv1 = fmaf(sK[buf][tt][kbase+j],   S[j],   kv1); }
            float kv = kv0 + kv1;
            kv += __shfl_xor_sync(0xffffffffu, kv, 8);
            kv += __shfl_xor_sync(0xffffffffu, kv, 16);
            float delta = (sV[buf][tt][dv] - kv) * bt;
            float ov0 = 0.f, ov1 = 0.f;
            #pragma unroll
            for (int j = 0; j < 8; j++) {
                S[j] = fmaf(sK[buf][tt][kbase+j], delta, S[j]);
                ov0  = fmaf(sQ[buf][tt][kbase+j], S[j], ov0);
            }
            #pragma unroll
            for (int j = 8; j < 16; j++) {
                S[j] = fmaf(sK[buf][tt][kbase+j], delta, S[j]);
                ov1  = fmaf(sQ[buf][tt][kbase+j], S[j], ov1);
            }
            float ov = ov0 + ov1;
            ov += __shfl_xor_sync(0xffffffffu, ov, 8);
            ov += __shfl_xor_sync(0xffffffffu, ov, 16);
            if ((lane >> 3) == 0)
                o[((size_t)b * TT + st * 8 + tt) * DD + chan + dv] = ov;
        }
    }
    #pragma unroll
    for (int j = 0; j < 16; j++)
        state[(((size_t)b * HH + h) * DK + kbase + j) * DV + dv] = S[j];
}

// ---------------- host launch ----------------
extern "C" void kernel_launch(void* const* d_in, const int* in_sizes, int n_in,
                              void* d_out, int out_size)
{
    const float* x    = (const float*)d_in[0];
    const float* anw  = (const float*)d_in[1];
    const float* Wq   = (const float*)d_in[2];
    const float* Wk   = (const float*)d_in[3];
    const float* Wv   = (const float*)d_in[4];
    const float* cq   = (const float*)d_in[5];
    const float* ck   = (const float*)d_in[6];
    const float* cv   = (const float*)d_in[7];
    const float* Wb   = (const float*)d_in[8];
    const float* Wa   = (const float*)d_in[9];
    const float* dtb  = (const float*)d_in[10];
    const float* Alog = (const float*)d_in[11];
    const float* ow   = (const float*)d_in[12];
    const float* Wo   = (const float*)d_in[13];
    const float* mlpw = (const float*)d_in[14];
    const float* Wg   = (const float*)d_in[15];
    const float* Wd   = (const float*)d_in[16];
    float* out = (float*)d_out;

    float *h1,*beta,*gex,*o,*h2,*sdump;
    __half *qkvh,*qch,*kch,*vch,*gmlh,*A2,*A3,*B2;
    cudaGetSymbolAddress((void**)&h1, g_h1);
    cudaGetSymbolAddress((void**)&qkvh, g_qkvh);
    cudaGetSymbolAddress((void**)&qch, g_qch);
    cudaGetSymbolAddress((void**)&kch, g_kch);
    cudaGetSymbolAddress((void**)&vch, g_vch);
    cudaGetSymbolAddress((void**)&beta, g_beta);
    cudaGetSymbolAddress((void**)&gex,  g_gex);
    cudaGetSymbolAddress((void**)&o,  g_o);
    cudaGetSymbolAddress((void**)&h2, g_h2);
    cudaGetSymbolAddress((void**)&gmlh, g_gmlh);
    cudaGetSymbolAddress((void**)&sdump, g_sdump);
    cudaGetSymbolAddress((void**)&A2, g_A2);
    cudaGetSymbolAddress((void**)&A3, g_A3);
    cudaGetSymbolAddress((void**)&B2, g_B2);

    cudaFuncSetAttribute(tc_gemm, cudaFuncAttributeMaxDynamicSharedMemorySize, GSMEM);

    float* state_out = (out_size >= ROWS*DD + BB*HH*DK*DV) ? (out + (size_t)ROWS*DD) : sdump;

    // ---- weight conversions up-front ----
    convB_qkv_kernel<<<dim3(32, 32, 3), 256>>>(Wq, Wk, Wv, B2 + OFF_QKV);
    convB_kernel<<<dim3(32, 32), 256>>>(Wo, B2 + OFF_O, 1024, 1024);
    convB_kernel<<<dim3(176, 32), 256>>>(Wg, B2 + OFF_G, 1024, 5632);
    convB_kernel<<<dim3(32, 88), 256>>>(Wd, B2 + OFF_D, 2816, 1024);
    // ---- pre-attn norm + fp16 (keeps fp32 h1 for proj) ----
    rmsnorm_halfA<<<ROWS, 256>>>(x, anw, h1, A2);
    // ---- QKV GEMM, fp16 out ----
    tc_gemm<<<dim3(24, 32), 128, GSMEM>>>(A2, B2 + OFF_QKV, nullptr, nullptr, qkvh, 3072, 1024);
    // ---- conv + silu (fp16), fused beta/gate projections ----
    conv_silu3_kernel<<<dim3(256, 3), 256>>>(qkvh, qch, kch, vch, cq, ck, cv);
    proj_beta_kernel<<<ROWS, 256>>>(h1, Wb, Wa, dtb, Alog, beta, gex);
    l2norm_qk_kernel<<<16384, 256>>>(qch, kch);
    // ---- scan (64 blocks, full head per block) ----
    scan_kernel<<<64, 256>>>(qch, kch, vch, beta, gex, o, state_out);
    // ---- h2 = x + o' @ Wo ----
    ornorm_halfA<<<ROWS, 256>>>(o, ow, A2);
    tc_gemm<<<dim3(8, 32), 128, GSMEM>>>(A2, B2 + OFF_O, x, h2, nullptr, 1024, 1024);
    // ---- MLP ----
    rmsnorm_halfA<<<ROWS, 256>>>(h2, mlpw, nullptr, A2);
    tc_gemm<<<dim3(44, 32), 128, GSMEM>>>(A2, B2 + OFF_G, nullptr, nullptr, gmlh, 5632, 1024);
    swiglu_halfA<<<dim3(6, ROWS), 256>>>(gmlh, A3);
    tc_gemm<<<dim3(8, 32), 128, GSMEM>>>(A3, B2 + OFF_D, h2, out, nullptr, 1024, 2816);
}

// round 17
// speedup vs baseline: 1.0510x; 1.0510x over previous
#include <cuda_runtime.h>
#include <cuda_fp16.h>
#include <cstdint>

// ---------------- problem constants ----------------
#define BB 4
#define TT 1024
#define DD 1024
#define HH 16
#define DK 64
#define DV 64
#define II 2816
#define ROWS (BB*TT)          // 4096

// B2 region offsets (halfs)
#define OFF_QKV 0
#define OFF_O   (3072*1024)
#define OFF_G   (OFF_O + 1024*1024)
#define OFF_D   (OFF_G + 5632*1024)
#define B2_TOTAL (OFF_D + 1024*2816)

// ---------------- scratch (device globals; no runtime alloc) ----------------
__device__ float  g_h1[ROWS*DD];
__device__ __half g_qkvh[(size_t)ROWS*3*DD];     // fp16 QKV GEMM output
__device__ float  g_qc[ROWS*DD];
__device__ float  g_kc[ROWS*DD];
__device__ float  g_vc[ROWS*DD];
__device__ float  g_beta[ROWS*HH];
__device__ float  g_gex[ROWS*HH];
__device__ float  g_o [ROWS*DD];
__device__ float  g_h2[ROWS*DD];
__device__ __half g_gmlh[(size_t)ROWS*2*II];     // fp16 Wg GEMM output
__device__ float  g_sdump[BB*HH*DK*DV];
__device__ __half g_A2[(size_t)ROWS*1024];       // hi-only activations, stride 1024
__device__ __half g_A3[(size_t)ROWS*II];         // mact, stride 2816
__device__ __half g_B2[(size_t)B2_TOTAL];        // all weights fp16, [N,K] each

// ================= helpers =================
__device__ __forceinline__ uint32_t smem_u32(const void* p) {
    uint32_t a;
    asm("{ .reg .u64 t; cvta.to.shared.u64 t, %1; cvt.u32.u64 %0, t; }" : "=r"(a) : "l"(p));
    return a;
}
__device__ __forceinline__ void cp16(uint32_t dst, const void* src) {
    asm volatile("cp.async.cg.shared.global [%0], [%1], 16;" :: "r"(dst), "l"(src) : "memory");
}
__device__ __forceinline__ void ldm_x4(uint32_t* r, uint32_t a) {
    asm volatile("ldmatrix.sync.aligned.m8n8.x4.shared.b16 {%0,%1,%2,%3}, [%4];"
                 : "=r"(r[0]), "=r"(r[1]), "=r"(r[2]), "=r"(r[3]) : "r"(a));
}
__device__ __forceinline__ void mma_f16(float* c, const uint32_t* a, const uint32_t* b) {
    asm volatile(
        "mma.sync.aligned.m16n8k16.row.col.f32.f16.f16.f32 "
        "{%0,%1,%2,%3}, {%4,%5,%6,%7}, {%8,%9}, {%0,%1,%2,%3};"
        : "+f"(c[0]), "+f"(c[1]), "+f"(c[2]), "+f"(c[3])
        : "r"(a[0]), "r"(a[1]), "r"(a[2]), "r"(a[3]), "r"(b[0]), "r"(b[1]));
}

// ================= fp16 HMMA GEMM =================
// C[4096,Nfull] = A[M,K] * B[N,K]^T.  Chalf != 0: fp16 output (no Add);
// else fp32 output (+Add).  CTA 128x128, 4 warps (2x2 of 64x64), BK=64,
// 3-stage cp.async, 2 CTAs/SM.
#define STG_BYTES 32768
#define GSMEM (3*STG_BYTES)    // 96 KB

__global__ void __launch_bounds__(128, 2)
tc_gemm(const __half* __restrict__ A, const __half* __restrict__ B,
        const float* __restrict__ Add, float* __restrict__ C,
        __half* __restrict__ Chalf, int Nfull, int K)
{
    extern __shared__ __align__(1024) char smem[];
    uint32_t sb = smem_u32(smem);
    const int tid = threadIdx.x;
    const int lane = tid & 31, w = tid >> 5;
    const int wm = w & 1, wn = w >> 1;
    const int m0 = blockIdx.y * 128, n0 = blockIdx.x * 128;
    const int NK = K >> 6;

    const __half* Ab = A + (size_t)m0 * K;
    const __half* Bb = B + (size_t)n0 * K;

    const int cr = tid >> 3, cc = tid & 7;
    const uint32_t cdst = (uint32_t)(cr * 128 + ((cc ^ (cr & 7)) << 4));

    float acc[4][8][4];
    #pragma unroll
    for (int i = 0; i < 4; i++)
        #pragma unroll
        for (int j = 0; j < 8; j++)
            #pragma unroll
            for (int l = 0; l < 4; l++) acc[i][j][l] = 0.f;

    const int rowA = wm * 64 + (lane & 15);
    const int rowB = wn * 64 + (lane & 7) + ((lane >> 4) << 3);
    uint32_t aChunk[4], bChunk[4];
    #pragma unroll
    for (int ks = 0; ks < 4; ks++) {
        aChunk[ks] = (uint32_t)(((ks * 2 + (lane >> 4)) ^ (rowA & 7)) << 4);
        bChunk[ks] = (uint32_t)(((ks * 2 + ((lane >> 3) & 1)) ^ (rowB & 7)) << 4);
    }

    #define LOAD_STAGE(kt, s) {                                                   \
        uint32_t sa = sb + (s) * STG_BYTES, sbB = sa + 16384;                      \
        const __half* Asrc = Ab + (size_t)cr * K + (kt) * 64 + cc * 8;             \
        const __half* Bsrc = Bb + (size_t)cr * K + (kt) * 64 + cc * 8;             \
        _Pragma("unroll")                                                          \
        for (int t = 0; t < 8; t++) {                                              \
            cp16(sa  + cdst + t * 2048, Asrc + (size_t)(t * 16) * K);              \
            cp16(sbB + cdst + t * 2048, Bsrc + (size_t)(t * 16) * K);              \
        }                                                                          \
        asm volatile("cp.async.commit_group;" ::: "memory");                       \
    }

    LOAD_STAGE(0, 0);
    LOAD_STAGE(1, 1);

    for (int kt = 0; kt < NK; kt++) {
        int s = kt - (kt / 3) * 3;
        asm volatile("cp.async.wait_group 1;" ::: "memory");
        __syncthreads();
        if (kt + 2 < NK) {
            int s2 = (kt + 2) - ((kt + 2) / 3) * 3;
            LOAD_STAGE(kt + 2, s2);
        } else {
            asm volatile("cp.async.commit_group;" ::: "memory");
        }
        uint32_t sa = sb + s * STG_BYTES, sbB = sa + 16384;
        uint32_t baseA = sa + (uint32_t)rowA * 128;
        uint32_t baseB = sbB + (uint32_t)rowB * 128;
        #pragma unroll
        for (int ks = 0; ks < 4; ks++) {
            uint32_t a[4][4], b[8][2];
            #pragma unroll
            for (int mt = 0; mt < 4; mt++)
                ldm_x4(a[mt], baseA + mt * 2048 + aChunk[ks]);
            #pragma unroll
            for (int np = 0; np < 4; np++) {
                uint32_t r[4];
                ldm_x4(r, baseB + np * 2048 + bChunk[ks]);
                b[2*np][0] = r[0]; b[2*np][1] = r[1];
                b[2*np+1][0] = r[2]; b[2*np+1][1] = r[3];
            }
            #pragma unroll
            for (int mt = 0; mt < 4; mt++)
                #pragma unroll
                for (int nt = 0; nt < 8; nt++)
                    mma_f16(acc[mt][nt], a[mt], b[nt]);
        }
        __syncthreads();
    }

    // ---- epilogue ----
    const int l4 = lane >> 2, l2 = (lane & 3) * 2;
    if (Chalf) {
        #pragma unroll
        for (int mt = 0; mt < 4; mt++) {
            size_t r0 = (size_t)(m0 + wm * 64 + mt * 16 + l4);
            #pragma unroll
            for (int nt = 0; nt < 8; nt++) {
                size_t cidx = r0 * Nfull + (n0 + wn * 64 + nt * 8 + l2);
                *(__half2*)(Chalf + cidx) = __floats2half2_rn(acc[mt][nt][0], acc[mt][nt][1]);
                *(__half2*)(Chalf + cidx + 8 * Nfull) = __floats2half2_rn(acc[mt][nt][2], acc[mt][nt][3]);
            }
        }
    } else {
        #pragma unroll
        for (int mt = 0; mt < 4; mt++) {
            size_t r0 = (size_t)(m0 + wm * 64 + mt * 16 + l4);
            #pragma unroll
            for (int nt = 0; nt < 8; nt++) {
                size_t cidx = r0 * Nfull + (n0 + wn * 64 + nt * 8 + l2);
                float2 v0 = make_float2(acc[mt][nt][0], acc[mt][nt][1]);
                float2 v1 = make_float2(acc[mt][nt][2], acc[mt][nt][3]);
                if (Add) {
                    float2 a0 = *(const float2*)(Add + cidx);
                    float2 a1 = *(const float2*)(Add + cidx + 8 * Nfull);
                    v0.x += a0.x; v0.y += a0.y; v1.x += a1.x; v1.y += a1.y;
                }
                *(float2*)(C + cidx) = v0;
                *(float2*)(C + cidx + 8 * Nfull) = v1;
            }
        }
    }
}

// ================= fused norm + fp16 conversion =================
__global__ __launch_bounds__(256) void rmsnorm_halfA(
    const float* __restrict__ in, const float* __restrict__ w,
    float* __restrict__ hout, __half* __restrict__ A2)
{
    int row = blockIdx.x;
    __shared__ float red[8];
    const float* p = in + (size_t)row * DD;
    float v0 = p[threadIdx.x];
    float v1 = p[threadIdx.x + 256];
    float v2 = p[threadIdx.x + 512];
    float v3 = p[threadIdx.x + 768];
    float ss = v0*v0 + v1*v1 + v2*v2 + v3*v3;
    #pragma unroll
    for (int off = 16; off; off >>= 1) ss += __shfl_xor_sync(0xffffffffu, ss, off);
    if ((threadIdx.x & 31) == 0) red[threadIdx.x >> 5] = ss;
    __syncthreads();
    float tot = 0.f;
    #pragma unroll
    for (int i = 0; i < 8; i++) tot += red[i];
    float r = rsqrtf(tot * (1.0f/1024.0f) + 1e-6f);
    __half* a = A2 + (size_t)row * 1024;
    float* q = hout ? hout + (size_t)row * DD : nullptr;
    float vals[4] = {v0, v1, v2, v3};
    #pragma unroll
    for (int i = 0; i < 4; i++) {
        int c = threadIdx.x + i * 256;
        float val = vals[i] * r * w[c];
        if (q) q[c] = val;
        a[c] = __float2half_rn(val);
    }
}

__global__ __launch_bounds__(256) void ornorm_halfA(
    const float* __restrict__ o, const float* __restrict__ w, __half* __restrict__ A2)
{
    int row = blockIdx.x, t = threadIdx.x;
    float4 vv = *(const float4*)(o + (size_t)row * 1024 + t * 4);
    float ss = vv.x*vv.x + vv.y*vv.y + vv.z*vv.z + vv.w*vv.w;
    ss += __shfl_xor_sync(0xffffffffu, ss, 1);
    ss += __shfl_xor_sync(0xffffffffu, ss, 2);
    ss += __shfl_xor_sync(0xffffffffu, ss, 4);
    ss += __shfl_xor_sync(0xffffffffu, ss, 8);
    float r = rsqrtf(ss * (1.0f/64.0f) + 1e-6f);
    __half2 h0 = __floats2half2_rn(vv.x * r * w[(t*4) & 63],   vv.y * r * w[(t*4+1) & 63]);
    __half2 h1 = __floats2half2_rn(vv.z * r * w[(t*4+2) & 63], vv.w * r * w[(t*4+3) & 63]);
    __half2* a = (__half2*)(A2 + (size_t)row * 1024 + t * 4);
    a[0] = h0; a[1] = h1;
}

// SwiGLU: fp16 gml in -> fp16 A3, stride 2816
__global__ __launch_bounds__(256) void swiglu_halfA(
    const __half* __restrict__ gml, __half* __restrict__ A3)
{
    int col2 = blockIdx.x * 256 + threadIdx.x;
    int row = blockIdx.y;
    if (col2 >= 1408) return;
    float2 g = __half22float2(*(const __half2*)(gml + (size_t)row * 5632 + col2 * 2));
    float2 y = __half22float2(*(const __half2*)(gml + (size_t)row * 5632 + 2816 + col2 * 2));
    float m0 = g.x / (1.f + expf(-g.x)) * y.x;
    float m1 = g.y / (1.f + expf(-g.y)) * y.y;
    *(__half2*)(A3 + (size_t)row * 2816 + col2 * 2) = __floats2half2_rn(m0, m1);
}

// W[K,N] -> B2[n][k] fp16 (transposed, single copy)
__global__ __launch_bounds__(256) void convB_kernel(
    const float* __restrict__ W, __half* __restrict__ B2, int K, int N)
{
    __shared__ float tile[32][33];
    int k0 = blockIdx.y * 32, n0 = blockIdx.x * 32;
    int tx = threadIdx.x & 31, ty = threadIdx.x >> 5;
    for (int i = ty; i < 32; i += 8)
        tile[i][tx] = W[(size_t)(k0 + i) * N + n0 + tx];
    __syncthreads();
    for (int i = ty; i < 32; i += 8) {
        size_t rb = (size_t)(n0 + i) * K;
        B2[rb + k0 + tx] = __float2half_rn(tile[tx][i]);
    }
}

__global__ __launch_bounds__(256) void convB_qkv_kernel(
    const float* __restrict__ Wq, const float* __restrict__ Wk, const float* __restrict__ Wv,
    __half* __restrict__ B2)
{
    const float* W = (blockIdx.z == 0) ? Wq : (blockIdx.z == 1) ? Wk : Wv;
    __shared__ float tile[32][33];
    int k0 = blockIdx.y * 32, n0 = blockIdx.x * 32;
    int tx = threadIdx.x & 31, ty = threadIdx.x >> 5;
    for (int i = ty; i < 32; i += 8)
        tile[i][tx] = W[(size_t)(k0 + i) * 1024 + n0 + tx];
    __syncthreads();
    for (int i = ty; i < 32; i += 8) {
        size_t rb = (size_t)(blockIdx.z * 1024 + n0 + i) * 1024;
        B2[rb + k0 + tx] = __float2half_rn(tile[tx][i]);
    }
}

// ---------------- fused b/a projections + gate math ----------------
__global__ __launch_bounds__(256) void proj_beta_kernel(
    const float* __restrict__ h, const float* __restrict__ Wb, const float* __restrict__ Wa,
    const float* __restrict__ dtb, const float* __restrict__ Alog,
    float* __restrict__ beta, float* __restrict__ gex)
{
    int row = blockIdx.x;
    __shared__ float sh[1024];
    for (int i = threadIdx.x; i < 1024; i += 256) sh[i] = h[(size_t)row * DD + i];
    __syncthreads();
    int grp = threadIdx.x >> 3, l = threadIdx.x & 7;
    const float* W = (grp < 16) ? Wb : Wa;
    int col = grp & 15;
    float s = 0.f;
    for (int k = l; k < 1024; k += 8) s += sh[k] * W[k * HH + col];
    s += __shfl_xor_sync(0xffffffffu, s, 1);
    s += __shfl_xor_sync(0xffffffffu, s, 2);
    s += __shfl_xor_sync(0xffffffffu, s, 4);
    if (l == 0) {
        if (grp < 16) {
            beta[(size_t)row * HH + col] = 2.f / (1.f + expf(-s));
        } else {
            float xv = s + dtb[col];
            float sp = (xv > 20.f) ? xv : log1pf(expf(xv));
            gex[(size_t)row * HH + col] = expf(-expf(Alog[col]) * sp);
        }
    }
}

// ---------------- causal depthwise conv (K=4) + SiLU, fp16 in / fp32 out ----------------
__global__ __launch_bounds__(256) void conv_silu3_kernel(
    const __half* __restrict__ qkv,
    float* __restrict__ qc, float* __restrict__ kc, float* __restrict__ vc,
    const float* __restrict__ cq, const float* __restrict__ ck, const float* __restrict__ cv)
{
    int which = blockIdx.y;
    const float* w = (which == 0) ? cq : (which == 1) ? ck : cv;
    float* out = (which == 0) ? qc : (which == 1) ? kc : vc;
    int inOff = which * 1024;

    int idx = blockIdx.x * 256 + threadIdx.x;
    int c   = idx & 1023;
    int tch = (idx >> 10) & 15;
    int b   = idx >> 14;
    int t0  = tch * 64;
    float w0 = w[c*4+0], w1 = w[c*4+1], w2 = w[c*4+2], w3 = w[c*4+3];
    size_t ibase = ((size_t)b * TT) * 3072 + inOff + c;
    size_t obase = ((size_t)b * TT) * DD + c;
    float xm3 = (t0 >= 3) ? __half2float(qkv[ibase + (size_t)(t0-3)*3072]) : 0.f;
    float xm2 = (t0 >= 2) ? __half2float(qkv[ibase + (size_t)(t0-2)*3072]) : 0.f;
    float xm1 = (t0 >= 1) ? __half2float(qkv[ibase + (size_t)(t0-1)*3072]) : 0.f;
    #pragma unroll 8
    for (int j = 0; j < 64; j++) {
        float xt = __half2float(qkv[ibase + (size_t)(t0+j)*3072]);
        float s  = xm3*w0 + xm2*w1 + xm1*w2 + xt*w3;
        out[obase + (size_t)(t0+j)*DD] = s / (1.f + expf(-s));
        xm3 = xm2; xm2 = xm1; xm1 = xt;
    }
}

// ---------------- L2 norm of q (with scale) and k ----------------
__global__ __launch_bounds__(256) void l2norm_qk_kernel(
    float* __restrict__ qc, float* __restrict__ kc)
{
    int gw = blockIdx.x * 8 + (threadIdx.x >> 5);
    int lane = threadIdx.x & 31;
    float* arr = (gw < 65536) ? qc : kc;
    size_t base = (size_t)(gw & 65535) * 64;
    float a = arr[base + lane], b = arr[base + 32 + lane];
    float ss = a*a + b*b;
    #pragma unroll
    for (int off = 16; off; off >>= 1) ss += __shfl_xor_sync(0xffffffffu, ss, off);
    float r = rsqrtf(ss + 1e-6f);
    if (gw < 65536) r *= 0.125f;
    arr[base + lane]      = a * r;
    arr[base + 32 + lane] = b * r;
}

// ---------------- gated delta-rule scan (8-step staging, split chains) ----------------
__global__ __launch_bounds__(256) void scan_kernel(
    const float* __restrict__ q, const float* __restrict__ k, const float* __restrict__ v,
    const float* __restrict__ beta, const float* __restrict__ gex,
    float* __restrict__ o, float* __restrict__ state)
{
    int hf   = blockIdx.x & 1;
    int h    = (blockIdx.x >> 1) & 15;
    int b    = blockIdx.x >> 5;
    int tid  = threadIdx.x, lane = tid & 31, w = tid >> 5;
    int dvL  = (w << 2) | (lane & 3);
    int dv   = hf * 32 + dvL;
    int kbase = (lane >> 2) << 3;

    __shared__ float sQ[2][8][64], sK[2][8][64], sV[2][8][32], sBe[2][8], sG[2][8];

    float S[8];
    #pragma unroll
    for (int j = 0; j < 8; j++) S[j] = 0.f;

    size_t chan = (size_t)h * 64;

    #define SCAN_LOAD(st, bf) {                                                          \
        size_t tb = (size_t)b * TT + (st) * 8;                                           \
        for (int i = tid; i < 1296; i += 256) {                                          \
            if (i < 512)       sQ[bf][i>>6][i&63] = q[(tb + (i>>6))*DD + chan + (i&63)]; \
            else if (i < 1024) { int j2 = i-512;                                         \
                sK[bf][j2>>6][j2&63] = k[(tb + (j2>>6))*DD + chan + (j2&63)]; }          \
            else if (i < 1280) { int j2 = i-1024;                                        \
                sV[bf][j2>>5][j2&31] = v[(tb + (j2>>5))*DD + chan + hf*32 + (j2&31)]; }  \
            else { int j2 = i-1280;                                                      \
                if (j2 < 8) sBe[bf][j2] = beta[(tb + j2)*HH + h];                        \
                else        sG[bf][j2-8] = gex[(tb + j2-8)*HH + h]; }                    \
        }                                                                                \
    }

    SCAN_LOAD(0, 0);

    for (int st = 0; st < 128; st++) {
        int buf = st & 1;
        __syncthreads();
        if (st + 1 < 128) SCAN_LOAD(st + 1, buf ^ 1);
        #pragma unroll 2
        for (int tt = 0; tt < 8; tt++) {
            float ge = sG[buf][tt], bt = sBe[buf][tt];
            float kv0 = 0.f, kv1 = 0.f;
            #pragma unroll
            for (int j = 0; j < 4; j++) { S[j] *= ge; kv0 = fmaf(sK[buf][tt][kbase+j], S[j], kv0); }
            #pragma unroll
            for (int j = 4; j < 8; j++) { S[j] *= ge; kv1 = fmaf(sK[buf][tt][kbase+j], S[j], kv1); }
            float kv = kv0 + kv1;
            kv += __shfl_xor_sync(0xffffffffu, kv, 4);
            kv += __shfl_xor_sync(0xffffffffu, kv, 8);
            kv += __shfl_xor_sync(0xffffffffu, kv, 16);
            float delta = (sV[buf][tt][dvL] - kv) * bt;
            float ov0 = 0.f, ov1 = 0.f;
            #pragma unroll
            for (int j = 0; j < 4; j++) {
                S[j] = fmaf(sK[buf][tt][kbase+j], delta, S[j]);
                ov0  = fmaf(sQ[buf][tt][kbase+j], S[j], ov0);
            }
            #pragma unroll
            for (int j = 4; j < 8; j++) {
                S[j] = fmaf(sK[buf][tt][kbase+j], delta, S[j]);
                ov1  = fmaf(sQ[buf][tt][kbase+j], S[j], ov1);
            }
            float ov = ov0 + ov1;
            ov += __shfl_xor_sync(0xffffffffu, ov, 4);
            ov += __shfl_xor_sync(0xffffffffu, ov, 8);
            ov += __shfl_xor_sync(0xffffffffu, ov, 16);
            if ((lane >> 2) == 0)
                o[((size_t)b * TT + st * 8 + tt) * DD + chan + dv] = ov;
        }
    }
    #pragma unroll
    for (int j = 0; j < 8; j++)
        state[(((size_t)b * HH + h) * DK + kbase + j) * DV + dv] = S[j];
}

// ---------------- host launch ----------------
extern "C" void kernel_launch(void* const* d_in, const int* in_sizes, int n_in,
                              void* d_out, int out_size)
{
    const float* x    = (const float*)d_in[0];
    const float* anw  = (const float*)d_in[1];
    const float* Wq   = (const float*)d_in[2];
    const float* Wk   = (const float*)d_in[3];
    const float* Wv   = (const float*)d_in[4];
    const float* cq   = (const float*)d_in[5];
    const float* ck   = (const float*)d_in[6];
    const float* cv   = (const float*)d_in[7];
    const float* Wb   = (const float*)d_in[8];
    const float* Wa   = (const float*)d_in[9];
    const float* dtb  = (const float*)d_in[10];
    const float* Alog = (const float*)d_in[11];
    const float* ow   = (const float*)d_in[12];
    const float* Wo   = (const float*)d_in[13];
    const float* mlpw = (const float*)d_in[14];
    const float* Wg   = (const float*)d_in[15];
    const float* Wd   = (const float*)d_in[16];
    float* out = (float*)d_out;

    float *h1,*qc,*kc,*vc,*beta,*gex,*o,*h2,*sdump;
    __half *qkvh,*gmlh,*A2,*A3,*B2;
    cudaGetSymbolAddress((void**)&h1, g_h1);
    cudaGetSymbolAddress((void**)&qkvh, g_qkvh);
    cudaGetSymbolAddress((void**)&qc, g_qc);
    cudaGetSymbolAddress((void**)&kc, g_kc);
    cudaGetSymbolAddress((void**)&vc, g_vc);
    cudaGetSymbolAddress((void**)&beta, g_beta);
    cudaGetSymbolAddress((void**)&gex,  g_gex);
    cudaGetSymbolAddress((void**)&o,  g_o);
    cudaGetSymbolAddress((void**)&h2, g_h2);
    cudaGetSymbolAddress((void**)&gmlh, g_gmlh);
    cudaGetSymbolAddress((void**)&sdump, g_sdump);
    cudaGetSymbolAddress((void**)&A2, g_A2);
    cudaGetSymbolAddress((void**)&A3, g_A3);
    cudaGetSymbolAddress((void**)&B2, g_B2);

    cudaFuncSetAttribute(tc_gemm, cudaFuncAttributeMaxDynamicSharedMemorySize, GSMEM);

    float* state_out = (out_size >= ROWS*DD + BB*HH*DK*DV) ? (out + (size_t)ROWS*DD) : sdump;

    // ---- weight conversions up-front ----
    convB_qkv_kernel<<<dim3(32, 32, 3), 256>>>(Wq, Wk, Wv, B2 + OFF_QKV);
    convB_kernel<<<dim3(32, 32), 256>>>(Wo, B2 + OFF_O, 1024, 1024);
    convB_kernel<<<dim3(176, 32), 256>>>(Wg, B2 + OFF_G, 1024, 5632);
    convB_kernel<<<dim3(32, 88), 256>>>(Wd, B2 + OFF_D, 2816, 1024);
    // ---- pre-attn norm + fp16 (keeps fp32 h1 for proj) ----
    rmsnorm_halfA<<<ROWS, 256>>>(x, anw, h1, A2);
    // ---- QKV GEMM, fp16 out ----
    tc_gemm<<<dim3(24, 32), 128, GSMEM>>>(A2, B2 + OFF_QKV, nullptr, nullptr, qkvh, 3072, 1024);
    // ---- conv + silu (fp16 in, fp32 out); fused beta/gate projections ----
    conv_silu3_kernel<<<dim3(256, 3), 256>>>(qkvh, qc, kc, vc, cq, ck, cv);
    proj_beta_kernel<<<ROWS, 256>>>(h1, Wb, Wa, dtb, Alog, beta, gex);
    l2norm_qk_kernel<<<16384, 256>>>(qc, kc);
    // ---- scan ----
    scan_kernel<<<128, 256>>>(qc, kc, vc, beta, gex, o, state_out);
    // ---- h2 = x + o' @ Wo ----
    ornorm_halfA<<<ROWS, 256>>>(o, ow, A2);
    tc_gemm<<<dim3(8, 32), 128, GSMEM>>>(A2, B2 + OFF_O, x, h2, nullptr, 1024, 1024);
    // ---- MLP ----
    rmsnorm_halfA<<<ROWS, 256>>>(h2, mlpw, nullptr, A2);
    tc_gemm<<<dim3(44, 32), 128, GSMEM>>>(A2, B2 + OFF_G, nullptr, nullptr, gmlh, 5632, 1024);
    swiglu_halfA<<<dim3(6, ROWS), 256>>>(gmlh, A3);
    tc_gemm<<<dim3(8, 32), 128, GSMEM>>>(A3, B2 + OFF_D, h2, out, nullptr, 1024, 2816);
}